// round 1
// baseline (speedup 1.0000x reference)
#include <cuda_runtime.h>
#include <cuda_bf16.h>
#include <math.h>

// ---------------- problem constants ----------------
#define BB    4
#define HH    192
#define WWI   192
#define DIM   256
#define HEADS 8
#define HD    32
#define WIN   8
#define SHIFT 4
#define HID   1024
#define NTOK  (BB * HH * WWI)          // 147456 tokens
#define NWH   (HH / WIN)               // 24
#define NWW   (WWI / WIN)              // 24
#define NWIN  (BB * NWH * NWW)         // 2304 windows
#define NN    (WIN * WIN)              // 64
#define EPSLN 1e-5f

// ---------------- scratch (device globals; no allocation allowed) ----------------
__device__ float g_hwin[(size_t)NTOK * DIM];   // LN1 output, window layout
__device__ float g_qkv [(size_t)NTOK * 3 * DIM];
__device__ float g_owin[(size_t)NTOK * DIM];   // attention output, window layout
__device__ float g_x2  [(size_t)NTOK * DIM];   // x + attn branch (token layout)
__device__ float g_m   [(size_t)NTOK * DIM];   // LN2 output
__device__ float g_fc1 [(size_t)NTOK * HID];

// map window-layout row -> token index (applies shift-roll)
__device__ __forceinline__ int map_row_to_token(int r) {
    int widx = r >> 6;            // window id
    int n    = r & 63;            // pos in window
    int b    = widx / (NWH * NWW);
    int rem  = widx % (NWH * NWW);
    int wh   = rem / NWW;
    int ww   = rem % NWW;
    int sh   = wh * WIN + (n >> 3);     // position in shifted frame
    int sw   = ww * WIN + (n & 7);
    int oh   = sh + SHIFT; if (oh >= HH)  oh -= HH;
    int ow   = sw + SHIFT; if (ow >= WWI) ow -= WWI;
    return b * (HH * WWI) + oh * WWI + ow;
}

// ---------------- LayerNorm (warp per 256-dim row) ----------------
// GATHER=1: row r is window-layout, read from in[token(r)], write out[r]
// GATHER=0: identity mapping
template <int GATHER>
__global__ __launch_bounds__(256) void ln_kernel(const float* __restrict__ in,
                                                 const float* __restrict__ gam,
                                                 const float* __restrict__ bet,
                                                 float* __restrict__ out) {
    int warp = (blockIdx.x * blockDim.x + threadIdx.x) >> 5;
    int lane = threadIdx.x & 31;
    if (warp >= NTOK) return;
    int r = warp;
    int src = GATHER ? map_row_to_token(r) : r;

    const float* xr = in + (size_t)src * DIM + lane * 8;
    float4 v0 = *(const float4*)(xr);
    float4 v1 = *(const float4*)(xr + 4);

    float s  = v0.x + v0.y + v0.z + v0.w + v1.x + v1.y + v1.z + v1.w;
    float sq = v0.x*v0.x + v0.y*v0.y + v0.z*v0.z + v0.w*v0.w
             + v1.x*v1.x + v1.y*v1.y + v1.z*v1.z + v1.w*v1.w;
    #pragma unroll
    for (int o = 16; o > 0; o >>= 1) {
        s  += __shfl_xor_sync(0xffffffffu, s,  o);
        sq += __shfl_xor_sync(0xffffffffu, sq, o);
    }
    float mean = s * (1.0f / DIM);
    float var  = sq * (1.0f / DIM) - mean * mean;
    float inv  = rsqrtf(var + EPSLN);

    const float* gp = gam + lane * 8;
    const float* bp = bet + lane * 8;
    float4 g0 = *(const float4*)(gp),     g1 = *(const float4*)(gp + 4);
    float4 b0 = *(const float4*)(bp),     b1 = *(const float4*)(bp + 4);
    float4 o0, o1;
    o0.x = (v0.x - mean) * inv * g0.x + b0.x;
    o0.y = (v0.y - mean) * inv * g0.y + b0.y;
    o0.z = (v0.z - mean) * inv * g0.z + b0.z;
    o0.w = (v0.w - mean) * inv * g0.w + b0.w;
    o1.x = (v1.x - mean) * inv * g1.x + b1.x;
    o1.y = (v1.y - mean) * inv * g1.y + b1.y;
    o1.z = (v1.z - mean) * inv * g1.z + b1.z;
    o1.w = (v1.w - mean) * inv * g1.w + b1.w;
    float* op = out + (size_t)r * DIM + lane * 8;
    *(float4*)(op)     = o0;
    *(float4*)(op + 4) = o1;
}

// ---------------- windowed attention: one block per (window, head) ----------------
__global__ __launch_bounds__(128) void attn_kernel(const float* __restrict__ qkv,
                                                   const float* __restrict__ bias_table,
                                                   float* __restrict__ owin) {
    __shared__ float qs[NN][HD + 1];
    __shared__ float ks[NN][HD + 1];
    __shared__ float vs[NN][HD + 1];
    __shared__ float sm[NN][NN + 1];

    const int widx = blockIdx.x;
    const int head = blockIdx.y;
    const int tid  = threadIdx.x;
    const float scale = 0.17677669529663688f;  // 1/sqrt(32)

    // load q,k,v (64 x 32 each) -- 512 float4 per tensor
    for (int i = tid; i < NN * (HD / 4); i += 128) {
        int n  = i >> 3;
        int d4 = (i & 7) * 4;
        size_t base = (size_t)(widx * NN + n) * (3 * DIM) + head * HD + d4;
        float4 q = *(const float4*)(qkv + base);
        float4 k = *(const float4*)(qkv + base + DIM);
        float4 v = *(const float4*)(qkv + base + 2 * DIM);
        qs[n][d4+0] = q.x * scale; qs[n][d4+1] = q.y * scale;
        qs[n][d4+2] = q.z * scale; qs[n][d4+3] = q.w * scale;
        ks[n][d4+0] = k.x; ks[n][d4+1] = k.y; ks[n][d4+2] = k.z; ks[n][d4+3] = k.w;
        vs[n][d4+0] = v.x; vs[n][d4+1] = v.y; vs[n][d4+2] = v.z; vs[n][d4+3] = v.w;
    }
    __syncthreads();

    // S = q*scale @ k^T + bias
    for (int idx = tid; idx < NN * NN; idx += 128) {
        int q = idx >> 6, k = idx & 63;
        float acc = 0.f;
        #pragma unroll
        for (int d = 0; d < HD; d++) acc += qs[q][d] * ks[k][d];
        int qi = q >> 3, qj = q & 7, ki = k >> 3, kj = k & 7;
        int ridx = (qi - ki + WIN - 1) * (2 * WIN - 1) + (qj - kj + WIN - 1);
        sm[q][k] = acc + bias_table[ridx * HEADS + head];
    }
    __syncthreads();

    // softmax per row
    if (tid < NN) {
        float mx = -1e30f;
        #pragma unroll
        for (int k = 0; k < NN; k++) mx = fmaxf(mx, sm[tid][k]);
        float s = 0.f;
        #pragma unroll
        for (int k = 0; k < NN; k++) { float e = __expf(sm[tid][k] - mx); sm[tid][k] = e; s += e; }
        float invs = 1.0f / s;
        #pragma unroll
        for (int k = 0; k < NN; k++) sm[tid][k] *= invs;
    }
    __syncthreads();

    // O = P @ V
    for (int idx = tid; idx < NN * HD; idx += 128) {
        int q = idx >> 5, d = idx & 31;
        float acc = 0.f;
        #pragma unroll
        for (int k = 0; k < NN; k++) acc += sm[q][k] * vs[k][d];
        owin[(size_t)(widx * NN + q) * DIM + head * HD + d] = acc;
    }
}

// ---------------- SGEMM: C = A(MxK) @ B(KxN) + bias, with fused epilogues ----------------
// EPI: 0=none  1=GELU  2=residual-add (token layout)  3=scatter(window->token)+residual
#define BM 128
#define BN 128
#define BKK 8
#define TM 8
#define TN 8

template <int EPI>
__global__ __launch_bounds__(256) void sgemm(int M, int N, int K,
                                             const float* __restrict__ A,
                                             const float* __restrict__ B,
                                             const float* __restrict__ bias,
                                             const float* __restrict__ resid,
                                             float* __restrict__ C) {
    __shared__ float As[BKK][BM];
    __shared__ float Bs[BKK][BN];

    const int tid = threadIdx.x;
    const int tx = tid % 16, ty = tid / 16;
    const int bRow = blockIdx.y * BM;
    const int bCol = blockIdx.x * BN;

    const int aRow = tid >> 1;
    const int aCol = (tid & 1) * 4;
    const int bRowL = tid >> 5;
    const int bCol4 = (tid & 31) * 4;

    const float* Aptr = A + (size_t)(bRow + aRow) * K + aCol;
    const float* Bptr = B + (size_t)bRowL * N + bCol + bCol4;

    float acc[TM][TN];
    #pragma unroll
    for (int i = 0; i < TM; i++)
        #pragma unroll
        for (int j = 0; j < TN; j++) acc[i][j] = 0.f;

    for (int k0 = 0; k0 < K; k0 += BKK) {
        float4 a = *(const float4*)(Aptr + k0);
        As[aCol + 0][aRow] = a.x;
        As[aCol + 1][aRow] = a.y;
        As[aCol + 2][aRow] = a.z;
        As[aCol + 3][aRow] = a.w;
        *(float4*)&Bs[bRowL][bCol4] = *(const float4*)(Bptr + (size_t)k0 * N);
        __syncthreads();

        #pragma unroll
        for (int k = 0; k < BKK; k++) {
            float rm[TM], rn[TN];
            #pragma unroll
            for (int i = 0; i < TM; i++) rm[i] = As[k][ty * TM + i];
            #pragma unroll
            for (int j = 0; j < TN; j++) rn[j] = Bs[k][tx * TN + j];
            #pragma unroll
            for (int i = 0; i < TM; i++)
                #pragma unroll
                for (int j = 0; j < TN; j++) acc[i][j] += rm[i] * rn[j];
        }
        __syncthreads();
    }

    #pragma unroll
    for (int i = 0; i < TM; i++) {
        int row = bRow + ty * TM + i;
        size_t outbase;
        const float* rbase = nullptr;
        if (EPI == 3) {
            int t = map_row_to_token(row);
            outbase = (size_t)t * N;
            rbase = resid + outbase;
        } else {
            outbase = (size_t)row * N;
            if (EPI == 2) rbase = resid + outbase;
        }
        #pragma unroll
        for (int j = 0; j < TN; j++) {
            int col = bCol + tx * TN + j;
            float v = acc[i][j] + bias[col];
            if (EPI == 1) v = 0.5f * v * (1.0f + erff(v * 0.70710678118654752f));
            if (EPI == 2 || EPI == 3) v += rbase[col];
            C[outbase + col] = v;
        }
    }
}

// ---------------- launch ----------------
extern "C" void kernel_launch(void* const* d_in, const int* in_sizes, int n_in,
                              void* d_out, int out_size) {
    const float* x          = (const float*)d_in[0];
    const float* norm1_g    = (const float*)d_in[1];
    const float* norm1_b    = (const float*)d_in[2];
    const float* qkv_w      = (const float*)d_in[3];
    const float* qkv_b      = (const float*)d_in[4];
    const float* bias_table = (const float*)d_in[5];
    const float* proj_w     = (const float*)d_in[6];
    const float* proj_b     = (const float*)d_in[7];
    const float* norm2_g    = (const float*)d_in[8];
    const float* norm2_b    = (const float*)d_in[9];
    const float* fc1_w      = (const float*)d_in[10];
    const float* fc1_b      = (const float*)d_in[11];
    const float* fc2_w      = (const float*)d_in[12];
    const float* fc2_b      = (const float*)d_in[13];
    float* out = (float*)d_out;

    float *p_hwin, *p_qkv, *p_owin, *p_x2, *p_m, *p_fc1;
    cudaGetSymbolAddress((void**)&p_hwin, g_hwin);
    cudaGetSymbolAddress((void**)&p_qkv,  g_qkv);
    cudaGetSymbolAddress((void**)&p_owin, g_owin);
    cudaGetSymbolAddress((void**)&p_x2,   g_x2);
    cudaGetSymbolAddress((void**)&p_m,    g_m);
    cudaGetSymbolAddress((void**)&p_fc1,  g_fc1);

    const int lnBlocks = NTOK / 8;           // 8 warps (rows) per 256-thread block
    const int mTiles = NTOK / BM;            // 1152

    // 1) LN1 fused with shift-roll + window gather
    ln_kernel<1><<<lnBlocks, 256>>>(x, norm1_g, norm1_b, p_hwin);

    // 2) QKV GEMM  (147456 x 256) @ (256 x 768)
    sgemm<0><<<dim3(768 / BN, mTiles), 256>>>(NTOK, 3 * DIM, DIM,
                                              p_hwin, qkv_w, qkv_b, nullptr, p_qkv);

    // 3) windowed attention
    attn_kernel<<<dim3(NWIN, HEADS), 128>>>(p_qkv, bias_table, p_owin);

    // 4) proj GEMM fused with window-reverse scatter + residual:  x2 = x + proj(o)
    sgemm<3><<<dim3(DIM / BN, mTiles), 256>>>(NTOK, DIM, DIM,
                                              p_owin, proj_w, proj_b, x, p_x2);

    // 5) LN2
    ln_kernel<0><<<lnBlocks, 256>>>(p_x2, norm2_g, norm2_b, p_m);

    // 6) fc1 GEMM + exact GELU
    sgemm<1><<<dim3(HID / BN, mTiles), 256>>>(NTOK, HID, DIM,
                                              p_m, fc1_w, fc1_b, nullptr, p_fc1);

    // 7) fc2 GEMM + residual -> final output
    sgemm<2><<<dim3(DIM / BN, mTiles), 256>>>(NTOK, DIM, HID,
                                              p_fc1, fc2_w, fc2_b, p_x2, out);
}

// round 2
// speedup vs baseline: 1.0013x; 1.0013x over previous
#include <cuda_runtime.h>
#include <cuda_bf16.h>
#include <math.h>

// ---------------- problem constants ----------------
#define BB    4
#define HH    192
#define WWI   192
#define DIM   256
#define HEADS 8
#define HD    32
#define WIN   8
#define SHIFT 4
#define HID   1024
#define NTOK  (BB * HH * WWI)          // 147456 tokens
#define NWH   (HH / WIN)               // 24
#define NWW   (WWI / WIN)              // 24
#define NWIN  (BB * NWH * NWW)         // 2304 windows
#define NN    (WIN * WIN)              // 64
#define EPSLN 1e-5f

// ---------------- scratch (device globals; no allocation allowed) ----------------
__device__ float g_hwin[(size_t)NTOK * DIM];   // LN1 output, window layout
__device__ float g_qkv [(size_t)NTOK * 3 * DIM];
__device__ float g_owin[(size_t)NTOK * DIM];   // attention output, window layout
__device__ float g_x2  [(size_t)NTOK * DIM];   // x + attn branch (token layout)
__device__ float g_m   [(size_t)NTOK * DIM];   // LN2 output
__device__ float g_fc1 [(size_t)NTOK * HID];

// map window-layout row -> token index (applies shift-roll)
__device__ __forceinline__ int map_row_to_token(int r) {
    int widx = r >> 6;            // window id
    int n    = r & 63;            // pos in window
    int b    = widx / (NWH * NWW);
    int rem  = widx % (NWH * NWW);
    int wh   = rem / NWW;
    int ww   = rem % NWW;
    int sh   = wh * WIN + (n >> 3);     // position in shifted frame
    int sw   = ww * WIN + (n & 7);
    int oh   = sh + SHIFT; if (oh >= HH)  oh -= HH;
    int ow   = sw + SHIFT; if (ow >= WWI) ow -= WWI;
    return b * (HH * WWI) + oh * WWI + ow;
}

// ---------------- LayerNorm (warp per 256-dim row) ----------------
// GATHER=1: row r is window-layout, read from in[token(r)], write out[r]
// GATHER=0: identity mapping
template <int GATHER>
__global__ __launch_bounds__(256) void ln_kernel(const float* __restrict__ in,
                                                 const float* __restrict__ gam,
                                                 const float* __restrict__ bet,
                                                 float* __restrict__ out) {
    int warp = (blockIdx.x * blockDim.x + threadIdx.x) >> 5;
    int lane = threadIdx.x & 31;
    if (warp >= NTOK) return;
    int r = warp;
    int src = GATHER ? map_row_to_token(r) : r;

    const float* xr = in + (size_t)src * DIM + lane * 8;
    float4 v0 = *(const float4*)(xr);
    float4 v1 = *(const float4*)(xr + 4);

    float s  = v0.x + v0.y + v0.z + v0.w + v1.x + v1.y + v1.z + v1.w;
    float sq = v0.x*v0.x + v0.y*v0.y + v0.z*v0.z + v0.w*v0.w
             + v1.x*v1.x + v1.y*v1.y + v1.z*v1.z + v1.w*v1.w;
    #pragma unroll
    for (int o = 16; o > 0; o >>= 1) {
        s  += __shfl_xor_sync(0xffffffffu, s,  o);
        sq += __shfl_xor_sync(0xffffffffu, sq, o);
    }
    float mean = s * (1.0f / DIM);
    float var  = sq * (1.0f / DIM) - mean * mean;
    float inv  = rsqrtf(var + EPSLN);

    const float* gp = gam + lane * 8;
    const float* bp = bet + lane * 8;
    float4 g0 = *(const float4*)(gp),     g1 = *(const float4*)(gp + 4);
    float4 b0 = *(const float4*)(bp),     b1 = *(const float4*)(bp + 4);
    float4 o0, o1;
    o0.x = (v0.x - mean) * inv * g0.x + b0.x;
    o0.y = (v0.y - mean) * inv * g0.y + b0.y;
    o0.z = (v0.z - mean) * inv * g0.z + b0.z;
    o0.w = (v0.w - mean) * inv * g0.w + b0.w;
    o1.x = (v1.x - mean) * inv * g1.x + b1.x;
    o1.y = (v1.y - mean) * inv * g1.y + b1.y;
    o1.z = (v1.z - mean) * inv * g1.z + b1.z;
    o1.w = (v1.w - mean) * inv * g1.w + b1.w;
    float* op = out + (size_t)r * DIM + lane * 8;
    *(float4*)(op)     = o0;
    *(float4*)(op + 4) = o1;
}

// ---------------- windowed attention: one block per (window, head) ----------------
__global__ __launch_bounds__(128) void attn_kernel(const float* __restrict__ qkv,
                                                   const float* __restrict__ bias_table,
                                                   float* __restrict__ owin) {
    __shared__ float qs[NN][HD + 1];
    __shared__ float ks[NN][HD + 1];
    __shared__ float vs[NN][HD + 1];
    __shared__ float sm[NN][NN + 1];

    const int widx = blockIdx.x;
    const int head = blockIdx.y;
    const int tid  = threadIdx.x;
    const float scale = 0.17677669529663688f;  // 1/sqrt(32)

    // load q,k,v (64 x 32 each) -- 512 float4 per tensor
    for (int i = tid; i < NN * (HD / 4); i += 128) {
        int n  = i >> 3;
        int d4 = (i & 7) * 4;
        size_t base = (size_t)(widx * NN + n) * (3 * DIM) + head * HD + d4;
        float4 q = *(const float4*)(qkv + base);
        float4 k = *(const float4*)(qkv + base + DIM);
        float4 v = *(const float4*)(qkv + base + 2 * DIM);
        qs[n][d4+0] = q.x * scale; qs[n][d4+1] = q.y * scale;
        qs[n][d4+2] = q.z * scale; qs[n][d4+3] = q.w * scale;
        ks[n][d4+0] = k.x; ks[n][d4+1] = k.y; ks[n][d4+2] = k.z; ks[n][d4+3] = k.w;
        vs[n][d4+0] = v.x; vs[n][d4+1] = v.y; vs[n][d4+2] = v.z; vs[n][d4+3] = v.w;
    }
    __syncthreads();

    // S = q*scale @ k^T + bias
    for (int idx = tid; idx < NN * NN; idx += 128) {
        int q = idx >> 6, k = idx & 63;
        float acc = 0.f;
        #pragma unroll
        for (int d = 0; d < HD; d++) acc += qs[q][d] * ks[k][d];
        int qi = q >> 3, qj = q & 7, ki = k >> 3, kj = k & 7;
        int ridx = (qi - ki + WIN - 1) * (2 * WIN - 1) + (qj - kj + WIN - 1);
        sm[q][k] = acc + bias_table[ridx * HEADS + head];
    }
    __syncthreads();

    // softmax per row
    if (tid < NN) {
        float mx = -1e30f;
        #pragma unroll
        for (int k = 0; k < NN; k++) mx = fmaxf(mx, sm[tid][k]);
        float s = 0.f;
        #pragma unroll
        for (int k = 0; k < NN; k++) { float e = __expf(sm[tid][k] - mx); sm[tid][k] = e; s += e; }
        float invs = 1.0f / s;
        #pragma unroll
        for (int k = 0; k < NN; k++) sm[tid][k] *= invs;
    }
    __syncthreads();

    // O = P @ V
    for (int idx = tid; idx < NN * HD; idx += 128) {
        int q = idx >> 5, d = idx & 31;
        float acc = 0.f;
        #pragma unroll
        for (int k = 0; k < NN; k++) acc += sm[q][k] * vs[k][d];
        owin[(size_t)(widx * NN + q) * DIM + head * HD + d] = acc;
    }
}

// ---------------- SGEMM: C = A(MxK) @ B(KxN) + bias, with fused epilogues ----------------
// EPI: 0=none  1=GELU  2=residual-add (token layout)  3=scatter(window->token)+residual
#define BM 128
#define BN 128
#define BKK 8
#define TM 8
#define TN 8

template <int EPI>
__global__ __launch_bounds__(256) void sgemm(int M, int N, int K,
                                             const float* __restrict__ A,
                                             const float* __restrict__ B,
                                             const float* __restrict__ bias,
                                             const float* __restrict__ resid,
                                             float* __restrict__ C) {
    __shared__ float As[BKK][BM];
    __shared__ float Bs[BKK][BN];

    const int tid = threadIdx.x;
    const int tx = tid % 16, ty = tid / 16;
    const int bRow = blockIdx.y * BM;
    const int bCol = blockIdx.x * BN;

    const int aRow = tid >> 1;
    const int aCol = (tid & 1) * 4;
    const int bRowL = tid >> 5;
    const int bCol4 = (tid & 31) * 4;

    const float* Aptr = A + (size_t)(bRow + aRow) * K + aCol;
    const float* Bptr = B + (size_t)bRowL * N + bCol + bCol4;

    float acc[TM][TN];
    #pragma unroll
    for (int i = 0; i < TM; i++)
        #pragma unroll
        for (int j = 0; j < TN; j++) acc[i][j] = 0.f;

    for (int k0 = 0; k0 < K; k0 += BKK) {
        float4 a = *(const float4*)(Aptr + k0);
        As[aCol + 0][aRow] = a.x;
        As[aCol + 1][aRow] = a.y;
        As[aCol + 2][aRow] = a.z;
        As[aCol + 3][aRow] = a.w;
        *(float4*)&Bs[bRowL][bCol4] = *(const float4*)(Bptr + (size_t)k0 * N);
        __syncthreads();

        #pragma unroll
        for (int k = 0; k < BKK; k++) {
            float rm[TM], rn[TN];
            #pragma unroll
            for (int i = 0; i < TM; i++) rm[i] = As[k][ty * TM + i];
            #pragma unroll
            for (int j = 0; j < TN; j++) rn[j] = Bs[k][tx * TN + j];
            #pragma unroll
            for (int i = 0; i < TM; i++)
                #pragma unroll
                for (int j = 0; j < TN; j++) acc[i][j] += rm[i] * rn[j];
        }
        __syncthreads();
    }

    #pragma unroll
    for (int i = 0; i < TM; i++) {
        int row = bRow + ty * TM + i;
        size_t outbase;
        const float* rbase = nullptr;
        if (EPI == 3) {
            int t = map_row_to_token(row);
            outbase = (size_t)t * N;
            rbase = resid + outbase;
        } else {
            outbase = (size_t)row * N;
            if (EPI == 2) rbase = resid + outbase;
        }
        #pragma unroll
        for (int j = 0; j < TN; j++) {
            int col = bCol + tx * TN + j;
            float v = acc[i][j] + bias[col];
            if (EPI == 1) v = 0.5f * v * (1.0f + erff(v * 0.70710678118654752f));
            if (EPI == 2 || EPI == 3) v += rbase[col];
            C[outbase + col] = v;
        }
    }
}

// ---------------- launch ----------------
extern "C" void kernel_launch(void* const* d_in, const int* in_sizes, int n_in,
                              void* d_out, int out_size) {
    const float* x          = (const float*)d_in[0];
    const float* norm1_g    = (const float*)d_in[1];
    const float* norm1_b    = (const float*)d_in[2];
    const float* qkv_w      = (const float*)d_in[3];
    const float* qkv_b      = (const float*)d_in[4];
    const float* bias_table = (const float*)d_in[5];
    const float* proj_w     = (const float*)d_in[6];
    const float* proj_b     = (const float*)d_in[7];
    const float* norm2_g    = (const float*)d_in[8];
    const float* norm2_b    = (const float*)d_in[9];
    const float* fc1_w      = (const float*)d_in[10];
    const float* fc1_b      = (const float*)d_in[11];
    const float* fc2_w      = (const float*)d_in[12];
    const float* fc2_b      = (const float*)d_in[13];
    float* out = (float*)d_out;

    float *p_hwin, *p_qkv, *p_owin, *p_x2, *p_m, *p_fc1;
    cudaGetSymbolAddress((void**)&p_hwin, g_hwin);
    cudaGetSymbolAddress((void**)&p_qkv,  g_qkv);
    cudaGetSymbolAddress((void**)&p_owin, g_owin);
    cudaGetSymbolAddress((void**)&p_x2,   g_x2);
    cudaGetSymbolAddress((void**)&p_m,    g_m);
    cudaGetSymbolAddress((void**)&p_fc1,  g_fc1);

    const int lnBlocks = NTOK / 8;           // 8 warps (rows) per 256-thread block
    const int mTiles = NTOK / BM;            // 1152

    // 1) LN1 fused with shift-roll + window gather
    ln_kernel<1><<<lnBlocks, 256>>>(x, norm1_g, norm1_b, p_hwin);

    // 2) QKV GEMM  (147456 x 256) @ (256 x 768)
    sgemm<0><<<dim3(768 / BN, mTiles), 256>>>(NTOK, 3 * DIM, DIM,
                                              p_hwin, qkv_w, qkv_b, nullptr, p_qkv);

    // 3) windowed attention
    attn_kernel<<<dim3(NWIN, HEADS), 128>>>(p_qkv, bias_table, p_owin);

    // 4) proj GEMM fused with window-reverse scatter + residual:  x2 = x + proj(o)
    sgemm<3><<<dim3(DIM / BN, mTiles), 256>>>(NTOK, DIM, DIM,
                                              p_owin, proj_w, proj_b, x, p_x2);

    // 5) LN2
    ln_kernel<0><<<lnBlocks, 256>>>(p_x2, norm2_g, norm2_b, p_m);

    // 6) fc1 GEMM + exact GELU
    sgemm<1><<<dim3(HID / BN, mTiles), 256>>>(NTOK, HID, DIM,
                                              p_m, fc1_w, fc1_b, nullptr, p_fc1);

    // 7) fc2 GEMM + residual -> final output
    sgemm<2><<<dim3(DIM / BN, mTiles), 256>>>(NTOK, DIM, HID,
                                              p_fc1, fc2_w, fc2_b, p_x2, out);
}